// round 1
// baseline (speedup 1.0000x reference)
#include <cuda_runtime.h>
#include <cuda_bf16.h>
#include <cstdint>

// Problem constants
#define BATCH   2
#define SEQ     2048
#define DMODEL  1024
#define DSTATE  16
#define DCONV   4
#define DINNER  2048
#define DTRANK  64
#define MTOK    (BATCH * SEQ)        // 4096 tokens
#define XZW     (2 * DINNER)         // 4096

// ---------------------------------------------------------------------------
// Scratch (static device globals; no runtime allocation allowed)
// ---------------------------------------------------------------------------
__device__ float g_xz  [(size_t)MTOK * XZW];     // in_proj output [m][4096] (xb | z)
__device__ float g_xc  [(size_t)MTOK * DINNER];  // conv+silu output
__device__ float g_xdbl[(size_t)MTOK * 96];      // x_proj output (dt_in|B|C)
__device__ float g_dt  [(size_t)MTOK * DINNER];  // softplus(dt)
__device__ float g_y   [(size_t)MTOK * DINNER];  // scan output (gated)

// ---------------------------------------------------------------------------
// Generic fp32 GEMM:  C[M,N] = A[M,K] * B[N,K]^T  (+ optional softplus+bias)
// Tiles: 128x128, K-step 8, 256 threads, 8x8 per-thread register tile.
// Requires M%128==0, N%128==0, K%8==0, 16B-aligned rows.
// ---------------------------------------------------------------------------
__device__ __forceinline__ float softplus_f(float x) {
    return (x > 20.f) ? x : log1pf(expf(x));
}

template <int ACT>
__global__ __launch_bounds__(256, 2)
void sgemm_nt(const float* __restrict__ A, int lda,
              const float* __restrict__ Bw, int ldb,
              const float* __restrict__ bias,
              float* __restrict__ C, int ldc,
              int M, int N, int K)
{
    __shared__ float sA[8][128];
    __shared__ float sB[8][128];

    const int tid = threadIdx.x;
    const int bm = blockIdx.y * 128;
    const int bn = blockIdx.x * 128;

    const int lrow = tid >> 1;          // 0..127
    const int lk   = (tid & 1) * 4;     // 0 or 4

    const float* Ap = A  + (size_t)(bm + lrow) * lda + lk;
    const float* Bp = Bw + (size_t)(bn + lrow) * ldb + lk;

    const int tx = tid & 15;            // col group
    const int ty = tid >> 4;            // row group

    float acc[8][8];
#pragma unroll
    for (int i = 0; i < 8; i++)
#pragma unroll
        for (int j = 0; j < 8; j++) acc[i][j] = 0.f;

    for (int kt = 0; kt < K; kt += 8) {
        float4 av = *(const float4*)(Ap + kt);
        float4 bv = *(const float4*)(Bp + kt);
        __syncthreads();
        sA[lk + 0][lrow] = av.x; sA[lk + 1][lrow] = av.y;
        sA[lk + 2][lrow] = av.z; sA[lk + 3][lrow] = av.w;
        sB[lk + 0][lrow] = bv.x; sB[lk + 1][lrow] = bv.y;
        sB[lk + 2][lrow] = bv.z; sB[lk + 3][lrow] = bv.w;
        __syncthreads();

#pragma unroll
        for (int kk = 0; kk < 8; kk++) {
            float a[8], b[8];
            float4 a0 = *(const float4*)&sA[kk][ty * 8];
            float4 a1 = *(const float4*)&sA[kk][ty * 8 + 4];
            float4 b0 = *(const float4*)&sB[kk][tx * 8];
            float4 b1 = *(const float4*)&sB[kk][tx * 8 + 4];
            a[0]=a0.x;a[1]=a0.y;a[2]=a0.z;a[3]=a0.w;a[4]=a1.x;a[5]=a1.y;a[6]=a1.z;a[7]=a1.w;
            b[0]=b0.x;b[1]=b0.y;b[2]=b0.z;b[3]=b0.w;b[4]=b1.x;b[5]=b1.y;b[6]=b1.z;b[7]=b1.w;
#pragma unroll
            for (int i = 0; i < 8; i++)
#pragma unroll
                for (int j = 0; j < 8; j++)
                    acc[i][j] = fmaf(a[i], b[j], acc[i][j]);
        }
    }

#pragma unroll
    for (int i = 0; i < 8; i++) {
        const int row = bm + ty * 8 + i;
        float* crow = C + (size_t)row * ldc + bn + tx * 8;
#pragma unroll
        for (int j = 0; j < 8; j++) {
            float v = acc[i][j];
            if (ACT == 1) v = softplus_f(v + bias[bn + tx * 8 + j]);
            crow[j] = v;
        }
    }
}

// ---------------------------------------------------------------------------
// Causal depthwise conv1d (width 4) + bias + SiLU.
// xb = first half of g_xz rows. Output g_xc [m][DINNER].
// grid: (DINNER/256, SEQ/16, BATCH), block 256
// ---------------------------------------------------------------------------
__global__ void conv_silu_kernel(const float* __restrict__ xz,
                                 const float* __restrict__ cw,
                                 const float* __restrict__ cb,
                                 float* __restrict__ xc)
{
    const int d  = blockIdx.x * 256 + threadIdx.x;
    const int l0 = blockIdx.y * 16;
    const int b  = blockIdx.z;

    const float w0 = cw[d * 4 + 0], w1 = cw[d * 4 + 1];
    const float w2 = cw[d * 4 + 2], w3 = cw[d * 4 + 3];
    const float bias = cb[d];

    const float* src = xz + ((size_t)b * SEQ) * XZW + d;   // stride XZW per l
    float xm3 = 0.f, xm2 = 0.f, xm1 = 0.f;
    if (l0 > 0) {
        xm3 = src[(size_t)(l0 - 3) * XZW];
        xm2 = src[(size_t)(l0 - 2) * XZW];
        xm1 = src[(size_t)(l0 - 1) * XZW];
    }
#pragma unroll
    for (int i = 0; i < 16; i++) {
        const int l = l0 + i;
        const float cur = src[(size_t)l * XZW];
        float v = fmaf(w0, xm3, fmaf(w1, xm2, fmaf(w2, xm1, fmaf(w3, cur, bias))));
        v = v / (1.f + expf(-v));                 // SiLU
        xc[((size_t)(b * SEQ + l)) * DINNER + d] = v;
        xm3 = xm2; xm2 = xm1; xm1 = cur;
    }
}

// ---------------------------------------------------------------------------
// x_proj: x_dbl[m][96] = xc[m][:] @ x_proj_w[96,2048]^T
// One block (128 threads) per token; row cached in smem; 96 threads compute.
// ---------------------------------------------------------------------------
__global__ void xproj_kernel(const float* __restrict__ xc,
                             const float* __restrict__ W,
                             float* __restrict__ xdbl)
{
    __shared__ float row[DINNER];
    const int m = blockIdx.x;
    const float* src = xc + (size_t)m * DINNER;
    for (int i = threadIdx.x; i < DINNER; i += 128) row[i] = src[i];
    __syncthreads();

    const int c = threadIdx.x;
    if (c < 96) {
        const float4* w4 = (const float4*)(W + (size_t)c * DINNER);
        const float4* r4 = (const float4*)row;
        float s = 0.f;
#pragma unroll 4
        for (int k = 0; k < DINNER / 4; k++) {
            float4 a = r4[k], w = w4[k];
            s += a.x * w.x + a.y * w.y + a.z * w.z + a.w * w.w;
        }
        xdbl[(size_t)m * 96 + c] = s;
    }
}

// ---------------------------------------------------------------------------
// Selective scan. 16 lanes per channel (one per state). 2 channels per warp.
// Includes skip term (+xc*D) and gating (* silu(z)).
// grid: 256 blocks x 256 threads  (4096 channels * 16 lanes)
// ---------------------------------------------------------------------------
__global__ __launch_bounds__(256)
void scan_kernel(const float* __restrict__ dt,
                 const float* __restrict__ xc,
                 const float* __restrict__ xdbl,
                 const float* __restrict__ xz,
                 const float* __restrict__ A_log,
                 const float* __restrict__ Dp,
                 float* __restrict__ y)
{
    const int gthread = blockIdx.x * blockDim.x + threadIdx.x;
    const int gch = gthread >> 4;          // 0..4095
    const int s   = threadIdx.x & 15;      // state index
    const int b   = gch >> 11;             // /DINNER
    const int d   = gch & (DINNER - 1);

    const float Ads = -__expf(A_log[d * DSTATE + s]);
    const float Dv  = Dp[d];

    const float* dtp = dt   + (size_t)b * SEQ * DINNER + d;
    const float* xcp = xc   + (size_t)b * SEQ * DINNER + d;
    const float* zp  = xz   + (size_t)b * SEQ * XZW + DINNER + d;
    const float* Bp  = xdbl + (size_t)b * SEQ * 96 + DTRANK + s;
    const float* Cp  = Bp + DSTATE;
    float* yp        = y    + (size_t)b * SEQ * DINNER + d;

    float h = 0.f;
    for (int l = 0; l < SEQ; l++) {
        const float dtv = dtp[(size_t)l * DINNER];
        const float xv  = xcp[(size_t)l * DINNER];
        const float Bv  = Bp[(size_t)l * 96];
        const float Cv  = Cp[(size_t)l * 96];
        const float dA  = __expf(dtv * Ads);
        h = fmaf(dA, h, dtv * xv * Bv);
        float ys = h * Cv;
        ys += __shfl_xor_sync(0xffffffffu, ys, 8);
        ys += __shfl_xor_sync(0xffffffffu, ys, 4);
        ys += __shfl_xor_sync(0xffffffffu, ys, 2);
        ys += __shfl_xor_sync(0xffffffffu, ys, 1);
        if (s == 0) {
            const float zv = zp[(size_t)l * XZW];
            const float gate = zv / (1.f + __expf(-zv));
            yp[(size_t)l * DINNER] = (ys + xv * Dv) * gate;
        }
    }
}

// ---------------------------------------------------------------------------
// kernel_launch
// inputs: x, in_proj_w, conv_w, conv_b, x_proj_w, dt_proj_w, dt_proj_b,
//         A_log, D_param, out_proj_w
// ---------------------------------------------------------------------------
extern "C" void kernel_launch(void* const* d_in, const int* in_sizes, int n_in,
                              void* d_out, int out_size)
{
    const float* x         = (const float*)d_in[0];
    const float* in_proj_w = (const float*)d_in[1];
    const float* conv_w    = (const float*)d_in[2];
    const float* conv_b    = (const float*)d_in[3];
    const float* x_proj_w  = (const float*)d_in[4];
    const float* dt_proj_w = (const float*)d_in[5];
    const float* dt_proj_b = (const float*)d_in[6];
    const float* A_log     = (const float*)d_in[7];
    const float* D_param   = (const float*)d_in[8];
    const float* out_proj_w= (const float*)d_in[9];
    float* out = (float*)d_out;

    float* xz   = nullptr; cudaGetSymbolAddress((void**)&xz,   g_xz);
    float* xc   = nullptr; cudaGetSymbolAddress((void**)&xc,   g_xc);
    float* xdbl = nullptr; cudaGetSymbolAddress((void**)&xdbl, g_xdbl);
    float* dt   = nullptr; cudaGetSymbolAddress((void**)&dt,   g_dt);
    float* y    = nullptr; cudaGetSymbolAddress((void**)&y,    g_y);

    // 1) in_proj: xz[4096,4096] = x[4096,1024] @ in_proj_w^T
    {
        dim3 grid(XZW / 128, MTOK / 128);
        sgemm_nt<0><<<grid, 256>>>(x, DMODEL, in_proj_w, DMODEL, nullptr,
                                   xz, XZW, MTOK, XZW, DMODEL);
    }
    // 2) conv + bias + silu -> xc
    {
        dim3 grid(DINNER / 256, SEQ / 16, BATCH);
        conv_silu_kernel<<<grid, 256>>>(xz, conv_w, conv_b, xc);
    }
    // 3) x_proj: xdbl[4096,96] = xc @ x_proj_w^T
    xproj_kernel<<<MTOK, 128>>>(xc, x_proj_w, xdbl);
    // 4) dt = softplus(dt_in @ dt_proj_w^T + b)   (A = xdbl with lda=96, K=64)
    {
        dim3 grid(DINNER / 128, MTOK / 128);
        sgemm_nt<1><<<grid, 256>>>(xdbl, 96, dt_proj_w, DTRANK, dt_proj_b,
                                   dt, DINNER, MTOK, DINNER, DTRANK);
    }
    // 5) selective scan + skip + gate -> y
    scan_kernel<<<(MTOK * DSTATE) / 256 * BATCH / BATCH, 256>>>(dt, xc, xdbl, xz,
                                                                A_log, D_param, y);
    // 6) out_proj: out[4096,1024] = y @ out_proj_w^T
    {
        dim3 grid(DMODEL / 128, MTOK / 128);
        sgemm_nt<0><<<grid, 256>>>(y, DINNER, out_proj_w, DINNER, nullptr,
                                   out, DMODEL, MTOK, DMODEL, DINNER);
    }
}

// round 3
// speedup vs baseline: 1.5917x; 1.5917x over previous
#include <cuda_runtime.h>
#include <cuda_bf16.h>
#include <cstdint>

typedef __nv_bfloat16 bf16;

// Problem constants
#define BATCH   2
#define SEQ     2048
#define DMODEL  1024
#define DSTATE  16
#define DINNER  2048
#define DTRANK  64
#define MTOK    (BATCH * SEQ)        // 4096 tokens
#define XZW     (2 * DINNER)         // 4096

// ---------------------------------------------------------------------------
// Scratch (static device globals; no runtime allocation allowed)
// ---------------------------------------------------------------------------
__device__ float g_xz  [(size_t)MTOK * XZW];     // in_proj output (xb | z) fp32
__device__ float g_xc  [(size_t)MTOK * DINNER];  // conv+silu output fp32
__device__ float g_xdbl[(size_t)MTOK * 96];      // x_proj output (dt_in|B|C) fp32
__device__ float g_dt  [(size_t)MTOK * DINNER];  // softplus(dt) fp32

__device__ bf16 g_xhi [(size_t)MTOK * DMODEL];
__device__ bf16 g_xlo [(size_t)MTOK * DMODEL];
__device__ bf16 g_wihi[(size_t)XZW * DMODEL];     // in_proj_w
__device__ bf16 g_wilo[(size_t)XZW * DMODEL];
__device__ bf16 g_wohi[(size_t)DMODEL * DINNER];  // out_proj_w
__device__ bf16 g_wolo[(size_t)DMODEL * DINNER];
__device__ bf16 g_wxhi[(size_t)128 * DINNER];     // x_proj_w padded 96->128 rows
__device__ bf16 g_wxlo[(size_t)128 * DINNER];
__device__ bf16 g_wdhi[(size_t)DINNER * DTRANK];  // dt_proj_w
__device__ bf16 g_wdlo[(size_t)DINNER * DTRANK];
__device__ bf16 g_xchi[(size_t)MTOK * DINNER];    // conv output
__device__ bf16 g_xclo[(size_t)MTOK * DINNER];
__device__ bf16 g_xdhi[(size_t)MTOK * 96];        // xdbl
__device__ bf16 g_xdlo[(size_t)MTOK * 96];
__device__ bf16 g_yhi [(size_t)MTOK * DINNER];    // scan output
__device__ bf16 g_ylo [(size_t)MTOK * DINNER];

// ---------------------------------------------------------------------------
// Helpers
// ---------------------------------------------------------------------------
#define SW128(o) ((o) ^ (((o) >> 3) & 0x70))

__device__ __forceinline__ uint32_t smem_u32(const void* p) {
    return (uint32_t)__cvta_generic_to_shared(p);
}

__device__ __forceinline__ void ldsm4(uint32_t r[4], uint32_t addr) {
    asm volatile("ldmatrix.sync.aligned.m8n8.x4.shared.b16 {%0,%1,%2,%3}, [%4];"
                 : "=r"(r[0]), "=r"(r[1]), "=r"(r[2]), "=r"(r[3]) : "r"(addr));
}

__device__ __forceinline__ void mma_bf16(float d[4], const uint32_t a[4], const uint32_t b[2]) {
    asm volatile("mma.sync.aligned.m16n8k16.row.col.f32.bf16.bf16.f32 "
                 "{%0,%1,%2,%3},{%4,%5,%6,%7},{%8,%9},{%0,%1,%2,%3};"
                 : "+f"(d[0]), "+f"(d[1]), "+f"(d[2]), "+f"(d[3])
                 : "r"(a[0]), "r"(a[1]), "r"(a[2]), "r"(a[3]), "r"(b[0]), "r"(b[1]));
}

#define CP_ASYNC16(dst, src) \
    asm volatile("cp.async.cg.shared.global [%0], [%1], 16;" :: "r"(dst), "l"(src))
#define CP_COMMIT() asm volatile("cp.async.commit_group;")

__device__ __forceinline__ float softplus_f(float x) {
    return (x > 20.f) ? x : log1pf(expf(x));
}

__device__ __forceinline__ void split2(float v, bf16& h, bf16& l) {
    h = __float2bfloat16(v);
    l = __float2bfloat16(v - __bfloat162float(h));
}

// ---------------------------------------------------------------------------
// bf16x3 warp-MMA GEMM: C[M,N] = A[M,K]*B[N,K]^T with fp32-equivalent accuracy
// (A,B given as bf16 hi/lo pairs; passes hi*hi + hi*lo + lo*hi).
// Tile 128x128, BK=64, 2-stage cp.async pipeline, 256 threads (8 warps, 64x32
// per warp). ACT==1: C = softplus(C + bias[col]).
// ---------------------------------------------------------------------------
#define GEMM_SMEM (2 * 65536)

template <int KTOT, int ACT>
__global__ __launch_bounds__(256, 1)
void mma_gemm(const bf16* __restrict__ Ahi, const bf16* __restrict__ Alo, int lda,
              const bf16* __restrict__ Bhi, const bf16* __restrict__ Blo, int ldb,
              const float* __restrict__ bias,
              float* __restrict__ C, int ldc, int n_store)
{
    extern __shared__ __align__(1024) char sm[];
    const int tid  = threadIdx.x;
    const int lane = tid & 31;
    const int w    = tid >> 5;
    const int wm   = w >> 2;          // 0..1  (64-row band)
    const int wn   = w & 3;           // 0..3  (32-col band)
    const int bm = blockIdx.y * 128, bn = blockIdx.x * 128;
    const uint32_t sbase = smem_u32(sm);

    constexpr int S = KTOT / 64;

    auto load_stage = [&](int st, int kt) {
        const uint32_t sb = sbase + st * 65536;
#pragma unroll
        for (int a = 0; a < 4; a++) {
            const bf16* base = (a == 0) ? Ahi : (a == 1) ? Alo : (a == 2) ? Bhi : Blo;
            const int  ld = (a < 2) ? lda : ldb;
            const int  rb = (a < 2) ? bm : bn;
            const uint32_t dstb = sb + a * 16384;
#pragma unroll
            for (int i = 0; i < 4; i++) {
                const int idx = tid + i * 256;
                const int row = idx >> 3, ch = idx & 7;
                const bf16* src = base + (size_t)(rb + row) * ld + kt + ch * 8;
                CP_ASYNC16(dstb + SW128(row * 128 + ch * 16), src);
            }
        }
        CP_COMMIT();
    };

    float acc[4][4][4];
#pragma unroll
    for (int mi = 0; mi < 4; mi++)
#pragma unroll
        for (int ni = 0; ni < 4; ni++)
#pragma unroll
            for (int j = 0; j < 4; j++) acc[mi][ni][j] = 0.f;

    load_stage(0, 0);
    if (S > 1) load_stage(1, 64);

    const int li = lane >> 3;        // ldmatrix lane-group 0..3
    const int lr = lane & 7;

    for (int s = 0; s < S; s++) {
        if (s + 1 < S) asm volatile("cp.async.wait_group 1;");
        else           asm volatile("cp.async.wait_group 0;");
        __syncthreads();

        const uint32_t sb  = sbase + (s & 1) * 65536;
        const uint32_t sAh = sb, sAl = sb + 16384, sBh = sb + 32768, sBl = sb + 49152;

#pragma unroll
        for (int kk = 0; kk < 4; kk++) {
            uint32_t ah[4][4], al[4][4], bh[4][2], bl[4][2];
#pragma unroll
            for (int mi = 0; mi < 4; mi++) {
                const uint32_t off = SW128(
                    (wm * 64 + mi * 16 + (li & 1) * 8 + lr) * 128 +
                    (kk * 16 + (li >> 1) * 8) * 2);
                ldsm4(ah[mi], sAh + off);
                ldsm4(al[mi], sAl + off);
            }
#pragma unroll
            for (int nj = 0; nj < 2; nj++) {
                const uint32_t off = SW128(
                    (wn * 32 + nj * 16 + (li >> 1) * 8 + lr) * 128 +
                    (kk * 16 + (li & 1) * 8) * 2);
                ldsm4(&bh[nj * 2][0], sBh + off);
                ldsm4(&bl[nj * 2][0], sBl + off);
            }
#pragma unroll
            for (int mi = 0; mi < 4; mi++)
#pragma unroll
                for (int ni = 0; ni < 4; ni++) {
                    mma_bf16(acc[mi][ni], ah[mi], bh[ni]);
                    mma_bf16(acc[mi][ni], ah[mi], bl[ni]);
                    mma_bf16(acc[mi][ni], al[mi], bh[ni]);
                }
        }
        __syncthreads();
        if (s + 2 < S) load_stage(s & 1, (s + 2) * 64);
    }

    // Epilogue: fragment -> global
    const int gid = lane >> 2, t4 = lane & 3;
#pragma unroll
    for (int mi = 0; mi < 4; mi++) {
        const int row0 = bm + wm * 64 + mi * 16 + gid;
#pragma unroll
        for (int ni = 0; ni < 4; ni++) {
            const int col = bn + wn * 32 + ni * 8 + t4 * 2;
            if (col >= n_store) continue;
            float v0 = acc[mi][ni][0], v1 = acc[mi][ni][1];
            float v2 = acc[mi][ni][2], v3 = acc[mi][ni][3];
            if (ACT == 1) {
                const float b0 = bias[col], b1 = bias[col + 1];
                v0 = softplus_f(v0 + b0); v1 = softplus_f(v1 + b1);
                v2 = softplus_f(v2 + b0); v3 = softplus_f(v3 + b1);
            }
            *(float2*)(C + (size_t)row0 * ldc + col)       = make_float2(v0, v1);
            *(float2*)(C + (size_t)(row0 + 8) * ldc + col) = make_float2(v2, v3);
        }
    }
}

// ---------------------------------------------------------------------------
// fp32 -> bf16 hi/lo split
// ---------------------------------------------------------------------------
__global__ void split_kernel(const float* __restrict__ src,
                             bf16* __restrict__ hi, bf16* __restrict__ lo, int n)
{
    const int i = (blockIdx.x * 256 + threadIdx.x) * 4;
    if (i >= n) return;
    float4 v = *(const float4*)(src + i);
    bf16 h0, l0, h1, l1, h2, l2, h3, l3;
    split2(v.x, h0, l0); split2(v.y, h1, l1);
    split2(v.z, h2, l2); split2(v.w, h3, l3);
    __nv_bfloat162 a, b;
    a.x = h0; a.y = h1; b.x = h2; b.y = h3;
    *(__nv_bfloat162*)(hi + i) = a; *(__nv_bfloat162*)(hi + i + 2) = b;
    a.x = l0; a.y = l1; b.x = l2; b.y = l3;
    *(__nv_bfloat162*)(lo + i) = a; *(__nv_bfloat162*)(lo + i + 2) = b;
}

// x_proj_w: [96][2048] -> padded [128][2048] hi/lo (rows >= 96 zero)
__global__ void split_pad_kernel(const float* __restrict__ src,
                                 bf16* __restrict__ hi, bf16* __restrict__ lo)
{
    const int i = blockIdx.x * 256 + threadIdx.x;   // over 128*2048
    const int row = i >> 11;
    float v = (row < 96) ? src[i] : 0.f;
    bf16 h, l;
    split2(v, h, l);
    hi[i] = h; lo[i] = l;
}

// ---------------------------------------------------------------------------
// Causal depthwise conv1d (width 4) + bias + SiLU -> xc (fp32 + bf16 hi/lo)
// ---------------------------------------------------------------------------
__global__ void conv_silu_kernel(const float* __restrict__ xz,
                                 const float* __restrict__ cw,
                                 const float* __restrict__ cb,
                                 float* __restrict__ xc,
                                 bf16* __restrict__ xchi,
                                 bf16* __restrict__ xclo)
{
    const int d  = blockIdx.x * 256 + threadIdx.x;
    const int l0 = blockIdx.y * 16;
    const int b  = blockIdx.z;

    const float w0 = cw[d * 4 + 0], w1 = cw[d * 4 + 1];
    const float w2 = cw[d * 4 + 2], w3 = cw[d * 4 + 3];
    const float bias = cb[d];

    const float* src = xz + ((size_t)b * SEQ) * XZW + d;
    float xm3 = 0.f, xm2 = 0.f, xm1 = 0.f;
    if (l0 > 0) {
        xm3 = src[(size_t)(l0 - 3) * XZW];
        xm2 = src[(size_t)(l0 - 2) * XZW];
        xm1 = src[(size_t)(l0 - 1) * XZW];
    }
#pragma unroll
    for (int i = 0; i < 16; i++) {
        const int l = l0 + i;
        const float cur = src[(size_t)l * XZW];
        float v = fmaf(w0, xm3, fmaf(w1, xm2, fmaf(w2, xm1, fmaf(w3, cur, bias))));
        v = v / (1.f + expf(-v));
        const size_t o = ((size_t)(b * SEQ + l)) * DINNER + d;
        xc[o] = v;
        bf16 h, lo_;
        split2(v, h, lo_);
        xchi[o] = h; xclo[o] = lo_;
        xm3 = xm2; xm2 = xm1; xm1 = cur;
    }
}

// ---------------------------------------------------------------------------
// Selective scan + skip + gate -> y (bf16 hi/lo)
// ---------------------------------------------------------------------------
__global__ __launch_bounds__(256)
void scan_kernel(const float* __restrict__ dt,
                 const float* __restrict__ xc,
                 const float* __restrict__ xdbl,
                 const float* __restrict__ xz,
                 const float* __restrict__ A_log,
                 const float* __restrict__ Dp,
                 bf16* __restrict__ yhi,
                 bf16* __restrict__ ylo)
{
    const int gthread = blockIdx.x * blockDim.x + threadIdx.x;
    const int gch = gthread >> 4;          // 0..4095
    const int s   = threadIdx.x & 15;      // state index
    const int b   = gch >> 11;
    const int d   = gch & (DINNER - 1);

    const float Ads = -__expf(A_log[d * DSTATE + s]);
    const float Dv  = Dp[d];

    const float* dtp = dt   + (size_t)b * SEQ * DINNER + d;
    const float* xcp = xc   + (size_t)b * SEQ * DINNER + d;
    const float* zp  = xz   + (size_t)b * SEQ * XZW + DINNER + d;
    const float* Bp  = xdbl + (size_t)b * SEQ * 96 + DTRANK + s;
    const float* Cp  = Bp + DSTATE;
    const size_t yb  = (size_t)b * SEQ * DINNER + d;

    float h = 0.f;
    for (int l = 0; l < SEQ; l++) {
        const float dtv = dtp[(size_t)l * DINNER];
        const float xv  = xcp[(size_t)l * DINNER];
        const float Bv  = Bp[(size_t)l * 96];
        const float Cv  = Cp[(size_t)l * 96];
        const float dA  = __expf(dtv * Ads);
        h = fmaf(dA, h, dtv * xv * Bv);
        float ys = h * Cv;
        ys += __shfl_xor_sync(0xffffffffu, ys, 8);
        ys += __shfl_xor_sync(0xffffffffu, ys, 4);
        ys += __shfl_xor_sync(0xffffffffu, ys, 2);
        ys += __shfl_xor_sync(0xffffffffu, ys, 1);
        if (s == 0) {
            const float zv = zp[(size_t)l * XZW];
            const float gate = zv / (1.f + __expf(-zv));
            const float v = (ys + xv * Dv) * gate;
            bf16 hh, ll;
            split2(v, hh, ll);
            yhi[yb + (size_t)l * DINNER] = hh;
            ylo[yb + (size_t)l * DINNER] = ll;
        }
    }
}

// ---------------------------------------------------------------------------
// kernel_launch
// ---------------------------------------------------------------------------
extern "C" void kernel_launch(void* const* d_in, const int* in_sizes, int n_in,
                              void* d_out, int out_size)
{
    const float* x          = (const float*)d_in[0];
    const float* in_proj_w  = (const float*)d_in[1];
    const float* conv_w     = (const float*)d_in[2];
    const float* conv_b     = (const float*)d_in[3];
    const float* x_proj_w   = (const float*)d_in[4];
    const float* dt_proj_w  = (const float*)d_in[5];
    const float* dt_proj_b  = (const float*)d_in[6];
    const float* A_log      = (const float*)d_in[7];
    const float* D_param    = (const float*)d_in[8];
    const float* out_proj_w = (const float*)d_in[9];
    float* out = (float*)d_out;

    float *xz, *xc, *xdbl, *dt;
    cudaGetSymbolAddress((void**)&xz,   g_xz);
    cudaGetSymbolAddress((void**)&xc,   g_xc);
    cudaGetSymbolAddress((void**)&xdbl, g_xdbl);
    cudaGetSymbolAddress((void**)&dt,   g_dt);
    bf16 *xhi, *xlo, *wihi, *wilo, *wohi, *wolo, *wxhi, *wxlo, *wdhi, *wdlo;
    bf16 *xchi, *xclo, *xdhi, *xdlo, *yhi, *ylo;
    cudaGetSymbolAddress((void**)&xhi,  g_xhi);  cudaGetSymbolAddress((void**)&xlo,  g_xlo);
    cudaGetSymbolAddress((void**)&wihi, g_wihi); cudaGetSymbolAddress((void**)&wilo, g_wilo);
    cudaGetSymbolAddress((void**)&wohi, g_wohi); cudaGetSymbolAddress((void**)&wolo, g_wolo);
    cudaGetSymbolAddress((void**)&wxhi, g_wxhi); cudaGetSymbolAddress((void**)&wxlo, g_wxlo);
    cudaGetSymbolAddress((void**)&wdhi, g_wdhi); cudaGetSymbolAddress((void**)&wdlo, g_wdlo);
    cudaGetSymbolAddress((void**)&xchi, g_xchi); cudaGetSymbolAddress((void**)&xclo, g_xclo);
    cudaGetSymbolAddress((void**)&xdhi, g_xdhi); cudaGetSymbolAddress((void**)&xdlo, g_xdlo);
    cudaGetSymbolAddress((void**)&yhi,  g_yhi);  cudaGetSymbolAddress((void**)&ylo,  g_ylo);

    cudaFuncSetAttribute(mma_gemm<1024, 0>, cudaFuncAttributeMaxDynamicSharedMemorySize, GEMM_SMEM);
    cudaFuncSetAttribute(mma_gemm<2048, 0>, cudaFuncAttributeMaxDynamicSharedMemorySize, GEMM_SMEM);
    cudaFuncSetAttribute(mma_gemm<64, 1>,   cudaFuncAttributeMaxDynamicSharedMemorySize, GEMM_SMEM);

    // 0) operand splits
    split_kernel<<<(MTOK * DMODEL) / 1024, 256>>>(x, xhi, xlo, MTOK * DMODEL);
    split_kernel<<<(XZW * DMODEL) / 1024, 256>>>(in_proj_w, wihi, wilo, XZW * DMODEL);
    split_kernel<<<(DMODEL * DINNER) / 1024, 256>>>(out_proj_w, wohi, wolo, DMODEL * DINNER);
    split_pad_kernel<<<(128 * DINNER) / 256, 256>>>(x_proj_w, wxhi, wxlo);
    split_kernel<<<(DINNER * DTRANK) / 1024, 256>>>(dt_proj_w, wdhi, wdlo, DINNER * DTRANK);

    // 1) in_proj: xz[4096,4096] = x @ in_proj_w^T   (K=1024)
    mma_gemm<1024, 0><<<dim3(XZW / 128, MTOK / 128), 256, GEMM_SMEM>>>(
        xhi, xlo, DMODEL, wihi, wilo, DMODEL, nullptr, xz, XZW, XZW);

    // 2) conv + bias + silu -> xc (+ hi/lo)
    conv_silu_kernel<<<dim3(DINNER / 256, SEQ / 16, BATCH), 256>>>(
        xz, conv_w, conv_b, xc, xchi, xclo);

    // 3) x_proj: xdbl[4096,96] = xc @ x_proj_w^T  (N padded to 128, store 96; K=2048)
    mma_gemm<2048, 0><<<dim3(1, MTOK / 128), 256, GEMM_SMEM>>>(
        xchi, xclo, DINNER, wxhi, wxlo, DINNER, nullptr, xdbl, 96, 96);

    // 3b) split xdbl -> hi/lo
    split_kernel<<<(MTOK * 96) / 1024, 256>>>(xdbl, xdhi, xdlo, MTOK * 96);

    // 4) dt = softplus(dt_in @ dt_proj_w^T + b)   (K=64, lda=96)
    mma_gemm<64, 1><<<dim3(DINNER / 128, MTOK / 128), 256, GEMM_SMEM>>>(
        xdhi, xdlo, 96, wdhi, wdlo, DTRANK, dt_proj_b, dt, DINNER, DINNER);

    // 5) selective scan + skip + gate -> y hi/lo
    scan_kernel<<<(MTOK * DSTATE) / 256, 256>>>(dt, xc, xdbl, xz, A_log, D_param, yhi, ylo);

    // 6) out_proj: out[4096,1024] = y @ out_proj_w^T  (K=2048)
    mma_gemm<2048, 0><<<dim3(DMODEL / 128, MTOK / 128), 256, GEMM_SMEM>>>(
        yhi, ylo, DINNER, wohi, wolo, DINNER, nullptr, out, DMODEL, DMODEL);
}